// round 7
// baseline (speedup 1.0000x reference)
#include <cuda_runtime.h>
#include <cuda_bf16.h>
#include <cstdint>

typedef unsigned long long ull;

__device__ __forceinline__ ull pack2(float a, float b) {
    ull r; asm("mov.b64 %0, {%1, %2};" : "=l"(r) : "f"(a), "f"(b)); return r;
}
__device__ __forceinline__ void unpack2(ull v, float& a, float& b) {
    asm("mov.b64 {%0, %1}, %2;" : "=f"(a), "=f"(b) : "l"(v));
}
__device__ __forceinline__ ull ffma2(ull a, ull b, ull c) {
    ull d; asm("fma.rn.f32x2 %0, %1, %2, %3;" : "=l"(d) : "l"(a), "l"(b), "l"(c)); return d;
}
__device__ __forceinline__ uint32_t bf16x2_of(float lo, float hi) {
    __nv_bfloat162 t = __floats2bfloat162_rn(lo, hi);
    return *reinterpret_cast<uint32_t*>(&t);
}
__device__ __forceinline__ uint32_t smem_u32(const void* p) {
    uint32_t a;
    asm("{ .reg .u64 t; cvta.to.shared.u64 t, %1; cvt.u32.u64 %0, t; }" : "=r"(a) : "l"(p));
    return a;
}
__device__ __forceinline__ void cp_async16(uint32_t s, const void* g) {
    asm volatile("cp.async.cg.shared.global [%0], [%1], 16;" :: "r"(s), "l"(g));
}
__device__ __forceinline__ void mma_bf16(
    float& d0, float& d1, float& d2, float& d3,
    uint32_t a0, uint32_t a1, uint32_t a2, uint32_t a3,
    uint32_t b0, uint32_t b1,
    float c0, float c1, float c2, float c3)
{
    asm volatile("mma.sync.aligned.m16n8k16.row.col.f32.bf16.bf16.f32 "
        "{%0,%1,%2,%3}, {%4,%5,%6,%7}, {%8,%9}, {%10,%11,%12,%13};"
        : "=f"(d0), "=f"(d1), "=f"(d2), "=f"(d3)
        : "r"(a0), "r"(a1), "r"(a2), "r"(a3), "r"(b0), "r"(b1),
          "f"(c0), "f"(c1), "f"(c2), "f"(c3));
}

// ------------- scratch (static __device__ arrays, no allocations) -------------
__device__ __align__(16) __nv_bfloat16 g_mono_hi[131072 * 32];
__device__ __align__(16) __nv_bfloat16 g_mono_lo[131072 * 32];
__device__ __align__(16) __nv_bfloat16 g_cv_hi[131072 * 32];
__device__ __align__(16) __nv_bfloat16 g_cv_lo[131072 * 32];
__device__ __align__(16) __nv_bfloat16 g_c1m_hi[32768 * 32];
__device__ __align__(16) __nv_bfloat16 g_c1m_lo[32768 * 32];
__device__ __align__(16) __nv_bfloat16 g_c1x_hi[32768 * 32];
__device__ __align__(16) __nv_bfloat16 g_c1x_lo[32768 * 32];
__device__ __align__(16) float g_featm[8192 * 32];               // fp32 px-major
__device__ __align__(16) float g_featx[8192 * 32];
__device__ __align__(16) __nv_bfloat16 g_qm[8192 * 32];          // bf16 px-major
__device__ __align__(16) __nv_bfloat16 g_qx[8192 * 32];
__device__ __align__(16) __nv_bfloat16 g_km[8192 * 32];
__device__ __align__(16) __nv_bfloat16 g_kx[8192 * 32];
__device__ __align__(16) __nv_bfloat16 g_vm[32 * 8192];          // bf16 channel-major
__device__ __align__(16) __nv_bfloat16 g_vx[32 * 8192];
__device__ float g_attc[2 * 8192 * 32];   // [0]=multi_out, [1]=mono_out (px-major)
__device__ __align__(16) __nv_bfloat16 g_r1_hi[131072 * 32];
__device__ __align__(16) __nv_bfloat16 g_r1_lo[131072 * 32];

// ---------------- transpose NCHW fp32 -> px-major bf16 hi/lo ----------------
__global__ __launch_bounds__(256) void to_pm_kernel(
    const float* __restrict__ src0, const float* __restrict__ src1)
{
    int br = blockIdx.y;
    const float* src = br ? src1 : src0;
    __nv_bfloat16* oh = br ? g_cv_hi : g_mono_hi;
    __nv_bfloat16* ol = br ? g_cv_lo : g_mono_lo;
    int px = blockIdx.x * 256 + threadIdx.x;
    uint32_t ph[16], pl[16];
#pragma unroll
    for (int c = 0; c < 16; c++) {
        float v0 = src[(size_t)(2 * c) * 131072 + px];
        float v1 = src[(size_t)(2 * c + 1) * 131072 + px];
        __nv_bfloat16 h0 = __float2bfloat16_rn(v0);
        __nv_bfloat16 h1 = __float2bfloat16_rn(v1);
        float l0 = v0 - __bfloat162float(h0);
        float l1 = v1 - __bfloat162float(h1);
        __nv_bfloat162 hh = { h0, h1 };
        ph[c] = *reinterpret_cast<uint32_t*>(&hh);
        pl[c] = bf16x2_of(l0, l1);
    }
    uint4* dh = (uint4*)(oh + (size_t)px * 32);
    uint4* dl = (uint4*)(ol + (size_t)px * 32);
#pragma unroll
    for (int c4 = 0; c4 < 4; c4++) {
        dh[c4] = make_uint4(ph[4 * c4], ph[4 * c4 + 1], ph[4 * c4 + 2], ph[4 * c4 + 3]);
        dl[c4] = make_uint4(pl[4 * c4], pl[4 * c4 + 1], pl[4 * c4 + 2], pl[4 * c4 + 3]);
    }
}

// ---------------- HMMA 3x3 conv (hi/lo split), px-major in/out ----------------
// A = input rows (16 px per warp), B = weights W[oc][k], K = 288 (tap-major, ic inner).
// OUT: 0 = bf16 hi/lo px-major, 1 = fp32 px-major, 2 = fp32 NCHW + gamma*upsampled att.
// TILE=1 (stride 1): CTA = 2 rows x 64 px with smem input tile (4 rows x 66 px, pitch 20 u32).
// TILE=0 (stride S): CTA = 128 consecutive px in one output row; direct predicated LDG.
struct HCArgs {
    const __nv_bfloat16 *ih0, *il0, *ih1, *il1;
    const float *w0, *b0, *w1, *b1;
    void *oh0, *ol0, *oh1, *ol1;      // OUT0: hi/lo; OUT1: oh = float* out
    float* outf;                      // OUT2
    const float* gammap;
    int Hin, Win, Wout, wsh;          // wsh = log2(Wout) for TILE=0
};

#define WP_N 148
#define TP_N 20

template <int S, int OUT, int TILE>
__global__ __launch_bounds__(256) void hconv_kernel(HCArgs a) {
    extern __shared__ __align__(16) uint32_t sm[];
    uint32_t* wp_hi = sm;                     // [32][148]
    uint32_t* wp_lo = sm + 32 * WP_N;
    float*    bs    = (float*)(sm + 2 * 32 * WP_N);
    uint32_t* th    = sm + 2 * 32 * WP_N + 32;         // [4][66*20]
    uint32_t* tl    = th + 4 * 66 * TP_N;

    int br = blockIdx.y;
    const __nv_bfloat16* inh = br ? a.ih1 : a.ih0;
    const __nv_bfloat16* inl = br ? a.il1 : a.il0;
    const float* w    = br ? a.w1 : a.w0;
    const float* bias = br ? a.b1 : a.b0;
    const uint32_t* inh32 = (const uint32_t*)inh;
    const uint32_t* inl32 = (const uint32_t*)inl;

    int tid = threadIdx.x, wid = tid >> 5, lane = tid & 31;
    int g = lane >> 2, t = lane & 3;

    // ---- stage weights (hi/lo split, packed ic-pairs) ----
    for (int i = tid; i < 4608; i += 256) {
        int oc = i / 144, kp = i % 144;
        int tap = kp >> 4, ic0 = (kp & 15) * 2;
        float w0v = w[(oc * 32 + ic0) * 9 + tap];
        float w1v = w[(oc * 32 + ic0 + 1) * 9 + tap];
        __nv_bfloat16 h0 = __float2bfloat16_rn(w0v);
        __nv_bfloat16 h1 = __float2bfloat16_rn(w1v);
        __nv_bfloat162 hh = { h0, h1 };
        wp_hi[oc * WP_N + kp] = *reinterpret_cast<uint32_t*>(&hh);
        wp_lo[oc * WP_N + kp] = bf16x2_of(w0v - __bfloat162float(h0), w1v - __bfloat162float(h1));
    }
    if (tid < 32) bs[tid] = bias[tid];

    // ---- geometry ----
    int y, xbase, y0 = 0, x0 = 0;
    if (TILE) {
        int xtiles = a.Win >> 6;
        int ty = blockIdx.x / xtiles, tx = blockIdx.x % xtiles;
        y0 = ty * 2; x0 = tx * 64;
        y = y0 + (wid >> 2);
        xbase = x0 + (wid & 3) * 16;
        // stage input tile: 4 rows (y0-1..y0+2) x 66 px (x0-1..x0+64), zero-padded
        for (int i = tid; i < 2112; i += 256) {
            int hb = (i >= 1056);
            int j = hb ? i - 1056 : i;
            int row = j / 264, rem = j % 264;
            int pxl = rem >> 2, c4 = rem & 3;
            int y_in = y0 - 1 + row, x_in = x0 - 1 + pxl;
            uint4 v = make_uint4(0, 0, 0, 0);
            if ((unsigned)y_in < (unsigned)a.Hin && (unsigned)x_in < (unsigned)a.Win)
                v = *(const uint4*)((hb ? inl : inh) + (size_t)(y_in * a.Win + x_in) * 32 + c4 * 8);
            *(uint4*)((hb ? tl : th) + row * (66 * TP_N) + pxl * TP_N + c4 * 4) = v;
        }
    } else {
        int px0 = blockIdx.x * 128 + wid * 16;
        y = px0 >> a.wsh;
        xbase = px0 & (a.Wout - 1);
    }
    __syncthreads();

    float C[4][4];
#pragma unroll
    for (int i = 0; i < 4; i++)
#pragma unroll
        for (int j = 0; j < 4; j++) C[i][j] = 0.f;

#pragma unroll
    for (int ky = 0; ky < 3; ky++) {
#pragma unroll
        for (int kx = 0; kx < 3; kx++) {
            int tap = ky * 3 + kx;
#pragma unroll
            for (int ich = 0; ich < 2; ich++) {
                int ks = tap * 2 + ich;
                uint32_t ah0, ah1, ah2, ah3, al0, al1, al2, al3;
                if (TILE) {
                    int base = (((wid >> 2) + ky) * 66 + (wid & 3) * 16 + kx) * TP_N + ich * 8;
                    ah0 = th[base + g * TP_N + t];
                    ah1 = th[base + (g + 8) * TP_N + t];
                    ah2 = th[base + g * TP_N + t + 4];
                    ah3 = th[base + (g + 8) * TP_N + t + 4];
                    al0 = tl[base + g * TP_N + t];
                    al1 = tl[base + (g + 8) * TP_N + t];
                    al2 = tl[base + g * TP_N + t + 4];
                    al3 = tl[base + (g + 8) * TP_N + t + 4];
                } else {
                    int y_in = S * y + ky - 1;
                    bool vy = (unsigned)y_in < (unsigned)a.Hin;
                    int xg  = S * (xbase + g) + kx - 1;
                    int xg8 = S * (xbase + g + 8) + kx - 1;
                    bool v0 = vy && (unsigned)xg  < (unsigned)a.Win;
                    bool v1 = vy && (unsigned)xg8 < (unsigned)a.Win;
                    size_t pg  = (size_t)(y_in * a.Win + xg)  * 16 + ich * 8 + t;
                    size_t pg8 = (size_t)(y_in * a.Win + xg8) * 16 + ich * 8 + t;
                    ah0 = v0 ? inh32[pg]      : 0u;
                    ah1 = v1 ? inh32[pg8]     : 0u;
                    ah2 = v0 ? inh32[pg + 4]  : 0u;
                    ah3 = v1 ? inh32[pg8 + 4] : 0u;
                    al0 = v0 ? inl32[pg]      : 0u;
                    al1 = v1 ? inl32[pg8]     : 0u;
                    al2 = v0 ? inl32[pg + 4]  : 0u;
                    al3 = v1 ? inl32[pg8 + 4] : 0u;
                }
#pragma unroll
                for (int nb = 0; nb < 4; nb++) {
                    int wrow = (nb * 8 + g) * WP_N + ks * 8 + t;
                    uint32_t bh0 = wp_hi[wrow], bh1 = wp_hi[wrow + 4];
                    uint32_t bl0 = wp_lo[wrow], bl1 = wp_lo[wrow + 4];
                    mma_bf16(C[nb][0], C[nb][1], C[nb][2], C[nb][3],
                             ah0, ah1, ah2, ah3, bh0, bh1,
                             C[nb][0], C[nb][1], C[nb][2], C[nb][3]);
                    mma_bf16(C[nb][0], C[nb][1], C[nb][2], C[nb][3],
                             ah0, ah1, ah2, ah3, bl0, bl1,
                             C[nb][0], C[nb][1], C[nb][2], C[nb][3]);
                    mma_bf16(C[nb][0], C[nb][1], C[nb][2], C[nb][3],
                             al0, al1, al2, al3, bh0, bh1,
                             C[nb][0], C[nb][1], C[nb][2], C[nb][3]);
                }
            }
        }
    }

    // ---- epilogue ----
    int pxg  = y * a.Wout + xbase + g;
    int pxg8 = pxg + 8;
    float gval = (OUT == 2) ? a.gammap[0] : 0.f;
#pragma unroll
    for (int nb = 0; nb < 4; nb++) {
        int oc0 = nb * 8 + 2 * t;
        float b0v = bs[oc0], b1v = bs[oc0 + 1];
        float v00 = fmaxf(C[nb][0] + b0v, 0.f);
        float v01 = fmaxf(C[nb][1] + b1v, 0.f);
        float v10 = fmaxf(C[nb][2] + b0v, 0.f);
        float v11 = fmaxf(C[nb][3] + b1v, 0.f);
        if (OUT == 0) {
            __nv_bfloat16* oh = (__nv_bfloat16*)(br ? a.oh1 : a.oh0);
            __nv_bfloat16* ol = (__nv_bfloat16*)(br ? a.ol1 : a.ol0);
            __nv_bfloat16 h00 = __float2bfloat16_rn(v00), h01 = __float2bfloat16_rn(v01);
            __nv_bfloat16 h10 = __float2bfloat16_rn(v10), h11 = __float2bfloat16_rn(v11);
            __nv_bfloat162 p0 = { h00, h01 }, p1 = { h10, h11 };
            ((uint32_t*)oh)[(size_t)pxg  * 16 + nb * 4 + t] = *reinterpret_cast<uint32_t*>(&p0);
            ((uint32_t*)oh)[(size_t)pxg8 * 16 + nb * 4 + t] = *reinterpret_cast<uint32_t*>(&p1);
            ((uint32_t*)ol)[(size_t)pxg  * 16 + nb * 4 + t] =
                bf16x2_of(v00 - __bfloat162float(h00), v01 - __bfloat162float(h01));
            ((uint32_t*)ol)[(size_t)pxg8 * 16 + nb * 4 + t] =
                bf16x2_of(v10 - __bfloat162float(h10), v11 - __bfloat162float(h11));
        } else if (OUT == 1) {
            float* of = (float*)(br ? a.oh1 : a.oh0);
            *(float2*)(of + (size_t)pxg  * 32 + oc0) = make_float2(v00, v01);
            *(float2*)(of + (size_t)pxg8 * 32 + oc0) = make_float2(v10, v11);
        } else {
            int xg = xbase + g;
            int ab0 = ((y >> 2) * 128 + (xg >> 2)) * 32;
            int ab1 = ((y >> 2) * 128 + ((xg + 8) >> 2)) * 32;
            float2 at0 = *(const float2*)(g_attc + ab0 + oc0);
            float2 at1 = *(const float2*)(g_attc + ab1 + oc0);
            a.outf[(size_t)oc0 * 131072 + pxg]        = v00 + gval * at0.x;
            a.outf[(size_t)(oc0 + 1) * 131072 + pxg]  = v01 + gval * at0.y;
            a.outf[(size_t)oc0 * 131072 + pxg8]       = v10 + gval * at1.x;
            a.outf[(size_t)(oc0 + 1) * 131072 + pxg8] = v11 + gval * at1.y;
        }
    }
}

// ---------------- 1x1 q/k/v projections: feat fp32 px-major in ----------------
struct QkvArgs {
    const float* w[6];
    const float* b[6];
    void* out[6];
};

__global__ __launch_bounds__(256) void qkv_kernel(QkvArgs a) {
    int y = blockIdx.y;
    const float* feat = (y < 3) ? g_featm : g_featx;
    __shared__ __align__(16) float wt[1024];   // [ic][oc]
    __shared__ float bsm[32];
    int tid = threadIdx.x;
    for (int i = tid; i < 1024; i += 256) {
        int oc = i >> 5, ic = i & 31;
        wt[ic * 32 + oc] = a.w[y][oc * 32 + ic];
    }
    if (tid < 32) bsm[tid] = a.b[y][tid];
    __syncthreads();

    int px = blockIdx.x * 256 + tid;
    float xv[32];
    {
        const float4* fp = (const float4*)(feat + (size_t)px * 32);
#pragma unroll
        for (int c4 = 0; c4 < 8; c4++) {
            float4 v = fp[c4];
            xv[4 * c4] = v.x; xv[4 * c4 + 1] = v.y; xv[4 * c4 + 2] = v.z; xv[4 * c4 + 3] = v.w;
        }
    }
    ull acc[16];
#pragma unroll
    for (int p = 0; p < 16; p++) acc[p] = pack2(bsm[2 * p], bsm[2 * p + 1]);
#pragma unroll
    for (int ic = 0; ic < 32; ic++) {
        ull x2 = pack2(xv[ic], xv[ic]);
        const ulonglong2* wp = (const ulonglong2*)(wt + ic * 32);
#pragma unroll
        for (int p2 = 0; p2 < 8; p2++) {
            ulonglong2 wv = wp[p2];
            acc[2 * p2]     = ffma2(x2, wv.x, acc[2 * p2]);
            acc[2 * p2 + 1] = ffma2(x2, wv.y, acc[2 * p2 + 1]);
        }
    }
    float vals[32];
#pragma unroll
    for (int p = 0; p < 16; p++) unpack2(acc[p], vals[2 * p], vals[2 * p + 1]);

    bool isv = (y == 2 || y == 5);
    if (!isv) {
        uint32_t pk[16];
#pragma unroll
        for (int c = 0; c < 16; c++) pk[c] = bf16x2_of(vals[2 * c], vals[2 * c + 1]);
        uint4* dst = (uint4*)((__nv_bfloat16*)a.out[y] + (size_t)px * 32);
#pragma unroll
        for (int c4 = 0; c4 < 4; c4++)
            dst[c4] = make_uint4(pk[4 * c4], pk[4 * c4 + 1], pk[4 * c4 + 2], pk[4 * c4 + 3]);
    } else {
        __nv_bfloat16* dst = (__nv_bfloat16*)a.out[y];
#pragma unroll
        for (int c = 0; c < 32; c++)
            dst[(size_t)c * 8192 + px] = __float2bfloat16_rn(vals[c]);
    }
}

// ---------------- flash attention on mma.sync (unchanged, validated) ----------------
__global__ __launch_bounds__(256, 1) void flash_mma_kernel() {
    const __nv_bfloat16 *Qb, *Kb, *Vb;
    if (blockIdx.y == 0) { Qb = g_qm; Kb = g_km; Vb = g_vx; }
    else                 { Qb = g_qx; Kb = g_kx; Vb = g_vm; }

    __shared__ __align__(16) unsigned char smK[2][8192];
    __shared__ __align__(16) unsigned char smV[2][8192];

    int tid  = threadIdx.x;
    int wid  = tid >> 5;
    int lane = tid & 31;
    int g    = lane >> 2;
    int t    = lane & 3;

    uint32_t skb[2] = { smem_u32(smK[0]), smem_u32(smK[1]) };
    uint32_t svb[2] = { smem_u32(smV[0]), smem_u32(smV[1]) };

    int q0 = blockIdx.x * 128 + wid * 16;
    uint32_t qa[2][4];
#pragma unroll
    for (int ks = 0; ks < 2; ks++) {
        const __nv_bfloat16* r0 = Qb + (size_t)(q0 + g) * 32;
        const __nv_bfloat16* r1 = Qb + (size_t)(q0 + g + 8) * 32;
        qa[ks][0] = *(const uint32_t*)(r0 + 16 * ks + 2 * t);
        qa[ks][1] = *(const uint32_t*)(r1 + 16 * ks + 2 * t);
        qa[ks][2] = *(const uint32_t*)(r0 + 16 * ks + 8 + 2 * t);
        qa[ks][3] = *(const uint32_t*)(r1 + 16 * ks + 8 + 2 * t);
    }

    float ob[4][4];
#pragma unroll
    for (int i = 0; i < 4; i++)
#pragma unroll
        for (int j = 0; j < 4; j++) ob[i][j] = 0.f;
    float sum_lo = 0.f, sum_hi = 0.f;

    for (int i = tid; i < 512; i += 256) {
        int key = i >> 2, c = i & 3;
        cp_async16(skb[0] + key * 64 + (((c + (key >> 1)) & 3) << 4),
                   (const char*)(Kb + (size_t)key * 32) + c * 16);
    }
    for (int i = tid; i < 512; i += 256) {
        int d = i >> 4, c = i & 15;
        cp_async16(svb[0] + d * 256 + (((c + d) & 15) << 4),
                   (const char*)(Vb + (size_t)d * 8192) + c * 16);
    }
    asm volatile("cp.async.commit_group;" ::: "memory");

    const int NT = 64;
    for (int tt = 0; tt < NT; tt++) {
        asm volatile("cp.async.wait_group 0;" ::: "memory");
        __syncthreads();
        if (tt + 1 < NT) {
            int nb2 = (tt + 1) & 1;
            int kb2 = (tt + 1) * 128;
            for (int i = tid; i < 512; i += 256) {
                int key = i >> 2, c = i & 3;
                cp_async16(skb[nb2] + key * 64 + (((c + (key >> 1)) & 3) << 4),
                           (const char*)(Kb + (size_t)(kb2 + key) * 32) + c * 16);
            }
            for (int i = tid; i < 512; i += 256) {
                int d = i >> 4, c = i & 15;
                cp_async16(svb[nb2] + d * 256 + (((c + d) & 15) << 4),
                           (const char*)(Vb + (size_t)d * 8192 + kb2) + c * 16);
            }
            asm volatile("cp.async.commit_group;" ::: "memory");
        }

        int buf = tt & 1;
        const uint32_t* kp = (const uint32_t*)smK[buf];
        const uint32_t* vp = (const uint32_t*)smV[buf];

        uint32_t pa[32];
#pragma unroll
        for (int nb = 0; nb < 16; nb++) {
            int key = nb * 8 + g;
            int rot = key >> 1;
            float c0 = 0.f, c1 = 0.f, c2 = 0.f, c3 = 0.f;
#pragma unroll
            for (int ks = 0; ks < 2; ks++) {
                uint32_t b0 = kp[key * 16 + (((2 * ks     + rot) & 3) << 2) + t];
                uint32_t b1 = kp[key * 16 + (((2 * ks + 1 + rot) & 3) << 2) + t];
                mma_bf16(c0, c1, c2, c3,
                         qa[ks][0], qa[ks][1], qa[ks][2], qa[ks][3],
                         b0, b1, c0, c1, c2, c3);
            }
            float e0 = __expf(c0), e1 = __expf(c1), e2 = __expf(c2), e3 = __expf(c3);
            sum_lo += e0 + e1;
            sum_hi += e2 + e3;
            int j = nb >> 1, h = nb & 1;
            pa[4 * j + 2 * h]     = bf16x2_of(e0, e1);
            pa[4 * j + 2 * h + 1] = bf16x2_of(e2, e3);
        }

#pragma unroll
        for (int j = 0; j < 8; j++) {
#pragma unroll
            for (int nbd = 0; nbd < 4; nbd++) {
                int d = nbd * 8 + g;
                uint32_t b0 = vp[d * 64 + (((2 * j     + d) & 15) << 2) + t];
                uint32_t b1 = vp[d * 64 + (((2 * j + 1 + d) & 15) << 2) + t];
                mma_bf16(ob[nbd][0], ob[nbd][1], ob[nbd][2], ob[nbd][3],
                         pa[4 * j], pa[4 * j + 1], pa[4 * j + 2], pa[4 * j + 3],
                         b0, b1,
                         ob[nbd][0], ob[nbd][1], ob[nbd][2], ob[nbd][3]);
            }
        }
    }

    sum_lo += __shfl_xor_sync(0xFFFFFFFFu, sum_lo, 1);
    sum_lo += __shfl_xor_sync(0xFFFFFFFFu, sum_lo, 2);
    sum_hi += __shfl_xor_sync(0xFFFFFFFFu, sum_hi, 1);
    sum_hi += __shfl_xor_sync(0xFFFFFFFFu, sum_hi, 2);
    float invLo = 1.0f / sum_lo;
    float invHi = 1.0f / sum_hi;

    float* base = g_attc + (size_t)blockIdx.y * 8192 * 32;
    float* rowA = base + (size_t)(q0 + g) * 32;
    float* rowB = base + (size_t)(q0 + g + 8) * 32;
#pragma unroll
    for (int nbd = 0; nbd < 4; nbd++) {
        int d = nbd * 8 + 2 * t;
        *(float2*)(rowA + d) = make_float2(ob[nbd][0] * invLo, ob[nbd][1] * invLo);
        *(float2*)(rowB + d) = make_float2(ob[nbd][2] * invHi, ob[nbd][3] * invHi);
    }
}

// ---------------- multi residual 1x1 + relu + fused epilogue (out ch 32..63) ----------------
__global__ __launch_bounds__(256) void xr_epi_kernel(
    const float* __restrict__ cv, const float* __restrict__ w,
    const float* __restrict__ b, const float* __restrict__ gammap,
    float* __restrict__ out)
{
    __shared__ __align__(16) float wt[1024];
    __shared__ float bsm[32];
    int tid = threadIdx.x;
    for (int i = tid; i < 1024; i += 256) {
        int oc = i >> 5, ic = i & 31;
        wt[ic * 32 + oc] = w[oc * 32 + ic];
    }
    if (tid < 32) bsm[tid] = b[tid];
    __syncthreads();

    int px = blockIdx.x * 256 + tid;
    ull acc[16];
#pragma unroll
    for (int p = 0; p < 16; p++) acc[p] = pack2(bsm[2 * p], bsm[2 * p + 1]);
    for (int ic = 0; ic < 32; ic++) {
        float x = cv[(size_t)ic * 131072 + px];
        ull x2 = pack2(x, x);
        const ulonglong2* wp = (const ulonglong2*)(wt + ic * 32);
#pragma unroll
        for (int p2 = 0; p2 < 8; p2++) {
            ulonglong2 wv = wp[p2];
            acc[2 * p2]     = ffma2(x2, wv.x, acc[2 * p2]);
            acc[2 * p2 + 1] = ffma2(x2, wv.y, acc[2 * p2 + 1]);
        }
    }
    float g = gammap[0];
    int yy = px >> 9, xx = px & 511;
    int fbase = 8192 * 32 + ((yy >> 2) * 128 + (xx >> 2)) * 32;
#pragma unroll
    for (int p = 0; p < 16; p++) {
        float va, vb; unpack2(acc[p], va, vb);
        int oc = 2 * p;
        out[(size_t)(32 + oc) * 131072 + px] = fmaxf(va, 0.f) + g * g_attc[fbase + oc];
        out[(size_t)(33 + oc) * 131072 + px] = fmaxf(vb, 0.f) + g * g_attc[fbase + oc + 1];
    }
}

// ---------------- host ----------------
#define SMEM_TILE (int)((2 * 32 * WP_N + 32 + 2 * 4 * 66 * TP_N) * 4)
#define SMEM_E    (int)((2 * 32 * WP_N + 32) * 4)

extern "C" void kernel_launch(void* const* d_in, const int* in_sizes, int n_in,
                              void* d_out, int out_size) {
    const float* mono  = (const float*)d_in[0];
    const float* cv    = (const float*)d_in[1];
    const float* me_w1 = (const float*)d_in[2];  const float* me_b1 = (const float*)d_in[3];
    const float* me_w2 = (const float*)d_in[4];  const float* me_b2 = (const float*)d_in[5];
    const float* xe_w1 = (const float*)d_in[6];  const float* xe_b1 = (const float*)d_in[7];
    const float* xe_w2 = (const float*)d_in[8];  const float* xe_b2 = (const float*)d_in[9];
    const float* mq_w  = (const float*)d_in[10]; const float* mq_b  = (const float*)d_in[11];
    const float* mk_w  = (const float*)d_in[12]; const float* mk_b  = (const float*)d_in[13];
    const float* mv_w  = (const float*)d_in[14]; const float* mv_b  = (const float*)d_in[15];
    const float* xq_w  = (const float*)d_in[16]; const float* xq_b  = (const float*)d_in[17];
    const float* xk_w  = (const float*)d_in[18]; const float* xk_b  = (const float*)d_in[19];
    const float* xv_w  = (const float*)d_in[20]; const float* xv_b  = (const float*)d_in[21];
    const float* mr_w1 = (const float*)d_in[22]; const float* mr_b1 = (const float*)d_in[23];
    const float* mr_w2 = (const float*)d_in[24]; const float* mr_b2 = (const float*)d_in[25];
    const float* xr_w  = (const float*)d_in[26]; const float* xr_b  = (const float*)d_in[27];
    const float* gamma = (const float*)d_in[28];
    float* out = (float*)d_out;

    static int smem_set = 0;
    if (!smem_set) {
        cudaFuncSetAttribute(hconv_kernel<2, 0, 0>, cudaFuncAttributeMaxDynamicSharedMemorySize, SMEM_E);
        cudaFuncSetAttribute(hconv_kernel<2, 1, 0>, cudaFuncAttributeMaxDynamicSharedMemorySize, SMEM_E);
        cudaFuncSetAttribute(hconv_kernel<1, 0, 1>, cudaFuncAttributeMaxDynamicSharedMemorySize, SMEM_TILE);
        cudaFuncSetAttribute(hconv_kernel<1, 2, 1>, cudaFuncAttributeMaxDynamicSharedMemorySize, SMEM_TILE);
        smem_set = 1;
    }

    void *p_mh, *p_ml, *p_ch, *p_cl, *p_c1mh, *p_c1ml, *p_c1xh, *p_c1xl;
    void *p_fm, *p_fx, *p_qm, *p_qx, *p_km, *p_kx, *p_vm, *p_vx, *p_r1h, *p_r1l;
    cudaGetSymbolAddress(&p_mh, g_mono_hi);  cudaGetSymbolAddress(&p_ml, g_mono_lo);
    cudaGetSymbolAddress(&p_ch, g_cv_hi);    cudaGetSymbolAddress(&p_cl, g_cv_lo);
    cudaGetSymbolAddress(&p_c1mh, g_c1m_hi); cudaGetSymbolAddress(&p_c1ml, g_c1m_lo);
    cudaGetSymbolAddress(&p_c1xh, g_c1x_hi); cudaGetSymbolAddress(&p_c1xl, g_c1x_lo);
    cudaGetSymbolAddress(&p_fm, g_featm);    cudaGetSymbolAddress(&p_fx, g_featx);
    cudaGetSymbolAddress(&p_qm, g_qm);       cudaGetSymbolAddress(&p_qx, g_qx);
    cudaGetSymbolAddress(&p_km, g_km);       cudaGetSymbolAddress(&p_kx, g_kx);
    cudaGetSymbolAddress(&p_vm, g_vm);       cudaGetSymbolAddress(&p_vx, g_vx);
    cudaGetSymbolAddress(&p_r1h, g_r1_hi);   cudaGetSymbolAddress(&p_r1l, g_r1_lo);

    // 1. transpose inputs to px-major bf16 hi/lo
    to_pm_kernel<<<dim3(512, 2), 256>>>(mono, cv);

    // 2. extractor conv1 (stride 2): 256x512 -> 128x256, both branches
    HCArgs e1{};
    e1.ih0 = (const __nv_bfloat16*)p_mh; e1.il0 = (const __nv_bfloat16*)p_ml;
    e1.ih1 = (const __nv_bfloat16*)p_ch; e1.il1 = (const __nv_bfloat16*)p_cl;
    e1.w0 = me_w1; e1.b0 = me_b1; e1.w1 = xe_w1; e1.b1 = xe_b1;
    e1.oh0 = p_c1mh; e1.ol0 = p_c1ml; e1.oh1 = p_c1xh; e1.ol1 = p_c1xl;
    e1.Hin = 256; e1.Win = 512; e1.Wout = 256; e1.wsh = 8;
    hconv_kernel<2, 0, 0><<<dim3(256, 2), 256, SMEM_E>>>(e1);

    // 3. extractor conv2 (stride 2): 128x256 -> 64x128 -> feat fp32 px-major
    HCArgs e2{};
    e2.ih0 = (const __nv_bfloat16*)p_c1mh; e2.il0 = (const __nv_bfloat16*)p_c1ml;
    e2.ih1 = (const __nv_bfloat16*)p_c1xh; e2.il1 = (const __nv_bfloat16*)p_c1xl;
    e2.w0 = me_w2; e2.b0 = me_b2; e2.w1 = xe_w2; e2.b1 = xe_b2;
    e2.oh0 = p_fm; e2.oh1 = p_fx;
    e2.Hin = 128; e2.Win = 256; e2.Wout = 128; e2.wsh = 7;
    hconv_kernel<2, 1, 0><<<dim3(64, 2), 256, SMEM_E>>>(e2);

    // 4. q/k/v projections
    QkvArgs qa;
    qa.w[0] = mq_w; qa.w[1] = mk_w; qa.w[2] = mv_w; qa.w[3] = xq_w; qa.w[4] = xk_w; qa.w[5] = xv_w;
    qa.b[0] = mq_b; qa.b[1] = mk_b; qa.b[2] = mv_b; qa.b[3] = xq_b; qa.b[4] = xk_b; qa.b[5] = xv_b;
    qa.out[0] = p_qm; qa.out[1] = p_km; qa.out[2] = p_vm;
    qa.out[3] = p_qx; qa.out[4] = p_kx; qa.out[5] = p_vx;
    qkv_kernel<<<dim3(32, 6), 256>>>(qa);

    // 5. two cross attentions
    flash_mma_kernel<<<dim3(64, 2), 256>>>();

    // 6. mono residual conv1 (stride 1): mono_pm -> r1 hi/lo
    HCArgs r1{};
    r1.ih0 = (const __nv_bfloat16*)p_mh; r1.il0 = (const __nv_bfloat16*)p_ml;
    r1.w0 = mr_w1; r1.b0 = mr_b1;
    r1.oh0 = p_r1h; r1.ol0 = p_r1l;
    r1.Hin = 256; r1.Win = 512; r1.Wout = 512; r1.wsh = 9;
    hconv_kernel<1, 0, 1><<<dim3(1024, 1), 256, SMEM_TILE>>>(r1);

    // 7. mono residual conv2 (stride 1) + epilogue -> out ch 0..31
    HCArgs r2{};
    r2.ih0 = (const __nv_bfloat16*)p_r1h; r2.il0 = (const __nv_bfloat16*)p_r1l;
    r2.w0 = mr_w2; r2.b0 = mr_b2;
    r2.outf = out; r2.gammap = gamma;
    r2.Hin = 256; r2.Win = 512; r2.Wout = 512; r2.wsh = 9;
    hconv_kernel<1, 2, 1><<<dim3(1024, 1), 256, SMEM_TILE>>>(r2);

    // 8. multi residual 1x1 + epilogue -> out ch 32..63
    xr_epi_kernel<<<512, 256>>>(cv, xr_w, xr_b, gamma, out);
}

// round 8
// speedup vs baseline: 1.1625x; 1.1625x over previous
#include <cuda_runtime.h>
#include <cuda_bf16.h>
#include <cstdint>

typedef unsigned long long ull;

__device__ __forceinline__ ull pack2(float a, float b) {
    ull r; asm("mov.b64 %0, {%1, %2};" : "=l"(r) : "f"(a), "f"(b)); return r;
}
__device__ __forceinline__ void unpack2(ull v, float& a, float& b) {
    asm("mov.b64 {%0, %1}, %2;" : "=f"(a), "=f"(b) : "l"(v));
}
__device__ __forceinline__ ull ffma2(ull a, ull b, ull c) {
    ull d; asm("fma.rn.f32x2 %0, %1, %2, %3;" : "=l"(d) : "l"(a), "l"(b), "l"(c)); return d;
}
__device__ __forceinline__ uint32_t bf16x2_of(float lo, float hi) {
    __nv_bfloat162 t = __floats2bfloat162_rn(lo, hi);
    return *reinterpret_cast<uint32_t*>(&t);
}
__device__ __forceinline__ uint32_t smem_u32(const void* p) {
    uint32_t a;
    asm("{ .reg .u64 t; cvta.to.shared.u64 t, %1; cvt.u32.u64 %0, t; }" : "=r"(a) : "l"(p));
    return a;
}
__device__ __forceinline__ void cp_async16(uint32_t s, const void* g) {
    asm volatile("cp.async.cg.shared.global [%0], [%1], 16;" :: "r"(s), "l"(g));
}
__device__ __forceinline__ void mma_bf16(
    float& d0, float& d1, float& d2, float& d3,
    uint32_t a0, uint32_t a1, uint32_t a2, uint32_t a3,
    uint32_t b0, uint32_t b1,
    float c0, float c1, float c2, float c3)
{
    asm volatile("mma.sync.aligned.m16n8k16.row.col.f32.bf16.bf16.f32 "
        "{%0,%1,%2,%3}, {%4,%5,%6,%7}, {%8,%9}, {%10,%11,%12,%13};"
        : "=f"(d0), "=f"(d1), "=f"(d2), "=f"(d3)
        : "r"(a0), "r"(a1), "r"(a2), "r"(a3), "r"(b0), "r"(b1),
          "f"(c0), "f"(c1), "f"(c2), "f"(c3));
}

// ------------- scratch (static __device__ arrays, no allocations) -------------
__device__ __align__(16) __nv_bfloat16 g_mono_hi[131072 * 32];
__device__ __align__(16) __nv_bfloat16 g_mono_lo[131072 * 32];
__device__ __align__(16) __nv_bfloat16 g_cv_hi[131072 * 32];
__device__ __align__(16) __nv_bfloat16 g_cv_lo[131072 * 32];
__device__ __align__(16) __nv_bfloat16 g_c1m_hi[32768 * 32];
__device__ __align__(16) __nv_bfloat16 g_c1m_lo[32768 * 32];
__device__ __align__(16) __nv_bfloat16 g_c1x_hi[32768 * 32];
__device__ __align__(16) __nv_bfloat16 g_c1x_lo[32768 * 32];
__device__ __align__(16) float g_featm[8192 * 32];               // fp32 px-major
__device__ __align__(16) float g_featx[8192 * 32];
__device__ __align__(16) __nv_bfloat16 g_qm[8192 * 32];          // bf16 px-major
__device__ __align__(16) __nv_bfloat16 g_qx[8192 * 32];
__device__ __align__(16) __nv_bfloat16 g_km[8192 * 32];
__device__ __align__(16) __nv_bfloat16 g_kx[8192 * 32];
__device__ __align__(16) __nv_bfloat16 g_vm[32 * 8192];          // bf16 channel-major
__device__ __align__(16) __nv_bfloat16 g_vx[32 * 8192];
__device__ float g_attc[2 * 8192 * 32];   // [0]=multi_out, [1]=mono_out (px-major)
__device__ __align__(16) __nv_bfloat16 g_r1_hi[131072 * 32];
__device__ __align__(16) __nv_bfloat16 g_r1_lo[131072 * 32];
// packed weights: 6 conv sets x [hi/lo][32 oc][148 kpairs-padded]
__device__ __align__(16) uint32_t g_wpack[6][2][32 * 148];
// packed qkv weights: 6 sets x [32 oc][20 kpairs-padded], single bf16
__device__ __align__(16) uint32_t g_qpack[6][32 * 20];

// ---------------- weight pre-pack ----------------
struct PrepArgs { const float* cw[6]; const float* qw[6]; };

__global__ __launch_bounds__(256) void prep_kernel(PrepArgs p) {
    int tid0 = blockIdx.x * 256 + threadIdx.x;
    int nth = gridDim.x * 256;
    for (int i = tid0; i < 6 * 4608; i += nth) {
        int set = i / 4608, j = i % 4608;
        int oc = j / 144, kp = j % 144;
        int tap = kp >> 4, ic0 = (kp & 15) * 2;
        const float* w = p.cw[set];
        float w0 = w[(oc * 32 + ic0) * 9 + tap];
        float w1 = w[(oc * 32 + ic0 + 1) * 9 + tap];
        __nv_bfloat16 h0 = __float2bfloat16_rn(w0);
        __nv_bfloat16 h1 = __float2bfloat16_rn(w1);
        __nv_bfloat162 hh = { h0, h1 };
        g_wpack[set][0][oc * 148 + kp] = *reinterpret_cast<uint32_t*>(&hh);
        g_wpack[set][1][oc * 148 + kp] =
            bf16x2_of(w0 - __bfloat162float(h0), w1 - __bfloat162float(h1));
    }
    for (int i = tid0; i < 6 * 512; i += nth) {
        int set = i / 512, j = i % 512;
        int oc = j / 16, c = j % 16;
        const float* w = p.qw[set];
        g_qpack[set][oc * 20 + c] = bf16x2_of(w[oc * 32 + 2 * c], w[oc * 32 + 2 * c + 1]);
    }
}

// ---------------- transpose NCHW fp32 -> px-major bf16 hi/lo ----------------
__global__ __launch_bounds__(256) void to_pm_kernel(
    const float* __restrict__ src0, const float* __restrict__ src1)
{
    int br = blockIdx.y;
    const float* src = br ? src1 : src0;
    __nv_bfloat16* oh = br ? g_cv_hi : g_mono_hi;
    __nv_bfloat16* ol = br ? g_cv_lo : g_mono_lo;
    int px = blockIdx.x * 256 + threadIdx.x;
    uint32_t ph[16], pl[16];
#pragma unroll
    for (int c = 0; c < 16; c++) {
        float v0 = src[(size_t)(2 * c) * 131072 + px];
        float v1 = src[(size_t)(2 * c + 1) * 131072 + px];
        __nv_bfloat16 h0 = __float2bfloat16_rn(v0);
        __nv_bfloat16 h1 = __float2bfloat16_rn(v1);
        __nv_bfloat162 hh = { h0, h1 };
        ph[c] = *reinterpret_cast<uint32_t*>(&hh);
        pl[c] = bf16x2_of(v0 - __bfloat162float(h0), v1 - __bfloat162float(h1));
    }
    uint4* dh = (uint4*)(oh + (size_t)px * 32);
    uint4* dl = (uint4*)(ol + (size_t)px * 32);
#pragma unroll
    for (int c4 = 0; c4 < 4; c4++) {
        dh[c4] = make_uint4(ph[4 * c4], ph[4 * c4 + 1], ph[4 * c4 + 2], ph[4 * c4 + 3]);
        dl[c4] = make_uint4(pl[4 * c4], pl[4 * c4 + 1], pl[4 * c4 + 2], pl[4 * c4 + 3]);
    }
}

// ---------------- HMMA 3x3 conv (hi/lo split), px-major in ----------------
// OUT: 0 = bf16 hi/lo px-major, 1 = fp32 px-major, 2 = fp32 NCHW relu (no att).
struct HCArgs {
    const __nv_bfloat16 *ih0, *il0, *ih1, *il1;
    const float *b0, *b1;
    void *oh0, *ol0, *oh1, *ol1;
    float* outf;
    int wset;                         // g_wpack index for branch 0 (branch1 = wset+1)
    int Hin, Win, Wout, wsh;
};

#define WP_N 148
#define TP_N 20

template <int S, int OUT, int TILE>
__global__ __launch_bounds__(256) void hconv_kernel(HCArgs a) {
    extern __shared__ __align__(16) uint32_t sm[];
    uint32_t* wp_hi = sm;                     // [32][148]
    uint32_t* wp_lo = sm + 32 * WP_N;
    float*    bs    = (float*)(sm + 2 * 32 * WP_N);
    uint32_t* th    = sm + 2 * 32 * WP_N + 32;         // [4][66*20]
    uint32_t* tl    = th + 4 * 66 * TP_N;

    int br = blockIdx.y;
    const __nv_bfloat16* inh = br ? a.ih1 : a.ih0;
    const __nv_bfloat16* inl = br ? a.il1 : a.il0;
    const float* bias = br ? a.b1 : a.b0;
    const uint32_t* inh32 = (const uint32_t*)inh;
    const uint32_t* inl32 = (const uint32_t*)inl;

    int tid = threadIdx.x, wid = tid >> 5, lane = tid & 31;
    int g = lane >> 2, t = lane & 3;

    // ---- stage weights: straight coalesced copy of pre-packed image ----
    {
        const uint4* src = (const uint4*)g_wpack[a.wset + br];
        uint4* dst = (uint4*)sm;
        for (int i = tid; i < 2368; i += 256) dst[i] = src[i];
    }
    if (tid < 32) bs[tid] = bias[tid];

    // ---- geometry ----
    int y, xbase, y0 = 0, x0 = 0;
    if (TILE) {
        int xtiles = a.Win >> 6;
        int ty = blockIdx.x / xtiles, tx = blockIdx.x % xtiles;
        y0 = ty * 2; x0 = tx * 64;
        y = y0 + (wid >> 2);
        xbase = x0 + (wid & 3) * 16;
        for (int i = tid; i < 2112; i += 256) {
            int hb = (i >= 1056);
            int j = hb ? i - 1056 : i;
            int row = j / 264, rem = j % 264;
            int pxl = rem >> 2, c4 = rem & 3;
            int y_in = y0 - 1 + row, x_in = x0 - 1 + pxl;
            uint4 v = make_uint4(0, 0, 0, 0);
            if ((unsigned)y_in < (unsigned)a.Hin && (unsigned)x_in < (unsigned)a.Win)
                v = *(const uint4*)((hb ? inl : inh) + (size_t)(y_in * a.Win + x_in) * 32 + c4 * 8);
            *(uint4*)((hb ? tl : th) + row * (66 * TP_N) + pxl * TP_N + c4 * 4) = v;
        }
    } else {
        int px0 = blockIdx.x * 128 + wid * 16;
        y = px0 >> a.wsh;
        xbase = px0 & (a.Wout - 1);
    }
    __syncthreads();

    float C[4][4];
#pragma unroll
    for (int i = 0; i < 4; i++)
#pragma unroll
        for (int j = 0; j < 4; j++) C[i][j] = 0.f;

#pragma unroll
    for (int ky = 0; ky < 3; ky++) {
#pragma unroll
        for (int kx = 0; kx < 3; kx++) {
            int tap = ky * 3 + kx;
#pragma unroll
            for (int ich = 0; ich < 2; ich++) {
                int ks = tap * 2 + ich;
                uint32_t ah0, ah1, ah2, ah3, al0, al1, al2, al3;
                if (TILE) {
                    int base = (((wid >> 2) + ky) * 66 + (wid & 3) * 16 + kx) * TP_N + ich * 8;
                    ah0 = th[base + g * TP_N + t];
                    ah1 = th[base + (g + 8) * TP_N + t];
                    ah2 = th[base + g * TP_N + t + 4];
                    ah3 = th[base + (g + 8) * TP_N + t + 4];
                    al0 = tl[base + g * TP_N + t];
                    al1 = tl[base + (g + 8) * TP_N + t];
                    al2 = tl[base + g * TP_N + t + 4];
                    al3 = tl[base + (g + 8) * TP_N + t + 4];
                } else {
                    int y_in = S * y + ky - 1;
                    bool vy = (unsigned)y_in < (unsigned)a.Hin;
                    int xg  = S * (xbase + g) + kx - 1;
                    int xg8 = S * (xbase + g + 8) + kx - 1;
                    bool v0 = vy && (unsigned)xg  < (unsigned)a.Win;
                    bool v1 = vy && (unsigned)xg8 < (unsigned)a.Win;
                    size_t pg  = (size_t)(y_in * a.Win + xg)  * 16 + ich * 8 + t;
                    size_t pg8 = (size_t)(y_in * a.Win + xg8) * 16 + ich * 8 + t;
                    ah0 = v0 ? inh32[pg]      : 0u;
                    ah1 = v1 ? inh32[pg8]     : 0u;
                    ah2 = v0 ? inh32[pg + 4]  : 0u;
                    ah3 = v1 ? inh32[pg8 + 4] : 0u;
                    al0 = v0 ? inl32[pg]      : 0u;
                    al1 = v1 ? inl32[pg8]     : 0u;
                    al2 = v0 ? inl32[pg + 4]  : 0u;
                    al3 = v1 ? inl32[pg8 + 4] : 0u;
                }
#pragma unroll
                for (int nb = 0; nb < 4; nb++) {
                    int wrow = (nb * 8 + g) * WP_N + ks * 8 + t;
                    uint32_t bh0 = wp_hi[wrow], bh1 = wp_hi[wrow + 4];
                    uint32_t bl0 = wp_lo[wrow], bl1 = wp_lo[wrow + 4];
                    mma_bf16(C[nb][0], C[nb][1], C[nb][2], C[nb][3],
                             ah0, ah1, ah2, ah3, bh0, bh1,
                             C[nb][0], C[nb][1], C[nb][2], C[nb][3]);
                    mma_bf16(C[nb][0], C[nb][1], C[nb][2], C[nb][3],
                             ah0, ah1, ah2, ah3, bl0, bl1,
                             C[nb][0], C[nb][1], C[nb][2], C[nb][3]);
                    mma_bf16(C[nb][0], C[nb][1], C[nb][2], C[nb][3],
                             al0, al1, al2, al3, bh0, bh1,
                             C[nb][0], C[nb][1], C[nb][2], C[nb][3]);
                }
            }
        }
    }

    // ---- epilogue ----
    int pxg  = y * a.Wout + xbase + g;
    int pxg8 = pxg + 8;
#pragma unroll
    for (int nb = 0; nb < 4; nb++) {
        int oc0 = nb * 8 + 2 * t;
        float b0v = bs[oc0], b1v = bs[oc0 + 1];
        float v00 = fmaxf(C[nb][0] + b0v, 0.f);
        float v01 = fmaxf(C[nb][1] + b1v, 0.f);
        float v10 = fmaxf(C[nb][2] + b0v, 0.f);
        float v11 = fmaxf(C[nb][3] + b1v, 0.f);
        if (OUT == 0) {
            __nv_bfloat16* oh = (__nv_bfloat16*)(br ? a.oh1 : a.oh0);
            __nv_bfloat16* ol = (__nv_bfloat16*)(br ? a.ol1 : a.ol0);
            __nv_bfloat16 h00 = __float2bfloat16_rn(v00), h01 = __float2bfloat16_rn(v01);
            __nv_bfloat16 h10 = __float2bfloat16_rn(v10), h11 = __float2bfloat16_rn(v11);
            __nv_bfloat162 p0 = { h00, h01 }, p1 = { h10, h11 };
            ((uint32_t*)oh)[(size_t)pxg  * 16 + nb * 4 + t] = *reinterpret_cast<uint32_t*>(&p0);
            ((uint32_t*)oh)[(size_t)pxg8 * 16 + nb * 4 + t] = *reinterpret_cast<uint32_t*>(&p1);
            ((uint32_t*)ol)[(size_t)pxg  * 16 + nb * 4 + t] =
                bf16x2_of(v00 - __bfloat162float(h00), v01 - __bfloat162float(h01));
            ((uint32_t*)ol)[(size_t)pxg8 * 16 + nb * 4 + t] =
                bf16x2_of(v10 - __bfloat162float(h10), v11 - __bfloat162float(h11));
        } else if (OUT == 1) {
            float* of = (float*)(br ? a.oh1 : a.oh0);
            *(float2*)(of + (size_t)pxg  * 32 + oc0) = make_float2(v00, v01);
            *(float2*)(of + (size_t)pxg8 * 32 + oc0) = make_float2(v10, v11);
        } else {
            a.outf[(size_t)oc0 * 131072 + pxg]        = v00;
            a.outf[(size_t)(oc0 + 1) * 131072 + pxg]  = v01;
            a.outf[(size_t)oc0 * 131072 + pxg8]       = v10;
            a.outf[(size_t)(oc0 + 1) * 131072 + pxg8] = v11;
        }
    }
}

// ---------------- fused HMMA qkv: feat fp32 -> q,k bf16 px-major; v bf16 ch-major ----------------
struct QkvHArgs { const float* b[6]; };

__global__ __launch_bounds__(256) void qkvh_kernel(QkvHArgs a) {
    __shared__ __align__(16) uint32_t qw[3 * 32 * 20];
    __shared__ float bsq[3][32];
    __shared__ __align__(16) __nv_bfloat16 vs[32 * 136];

    int br = blockIdx.y;
    const float* feat = br ? g_featx : g_featm;
    int tid = threadIdx.x, wid = tid >> 5, lane = tid & 31;
    int g = lane >> 2, t = lane & 3;

    {
        const uint4* src = (const uint4*)g_qpack[br * 3];
        for (int i = tid; i < 480; i += 256) ((uint4*)qw)[i] = src[i];
    }
    if (tid < 96) bsq[tid >> 5][tid & 31] = a.b[br * 3 + (tid >> 5)][tid & 31];
    __syncthreads();

    int q0 = blockIdx.x * 128 + wid * 16;
    uint32_t qa[2][4];
    {
        const float* r0 = feat + (size_t)(q0 + g) * 32;
        const float* r1 = feat + (size_t)(q0 + g + 8) * 32;
#pragma unroll
        for (int ks = 0; ks < 2; ks++) {
            qa[ks][0] = bf16x2_of(r0[16 * ks + 2 * t],     r0[16 * ks + 2 * t + 1]);
            qa[ks][1] = bf16x2_of(r1[16 * ks + 2 * t],     r1[16 * ks + 2 * t + 1]);
            qa[ks][2] = bf16x2_of(r0[16 * ks + 8 + 2 * t], r0[16 * ks + 8 + 2 * t + 1]);
            qa[ks][3] = bf16x2_of(r1[16 * ks + 8 + 2 * t], r1[16 * ks + 8 + 2 * t + 1]);
        }
    }

#pragma unroll
    for (int proj = 0; proj < 3; proj++) {
        float C[4][4];
#pragma unroll
        for (int i = 0; i < 4; i++)
#pragma unroll
            for (int j = 0; j < 4; j++) C[i][j] = 0.f;
#pragma unroll
        for (int ks = 0; ks < 2; ks++) {
#pragma unroll
            for (int nb = 0; nb < 4; nb++) {
                int wrow = proj * 640 + (nb * 8 + g) * 20 + ks * 8 + t;
                mma_bf16(C[nb][0], C[nb][1], C[nb][2], C[nb][3],
                         qa[ks][0], qa[ks][1], qa[ks][2], qa[ks][3],
                         qw[wrow], qw[wrow + 4],
                         C[nb][0], C[nb][1], C[nb][2], C[nb][3]);
            }
        }
        if (proj < 2) {
            __nv_bfloat16* dst;
            if (proj == 0) dst = br ? g_qx : g_qm;
            else           dst = br ? g_kx : g_km;
            int pxg = q0 + g, pxg8 = pxg + 8;
#pragma unroll
            for (int nb = 0; nb < 4; nb++) {
                int oc0 = nb * 8 + 2 * t;
                float b0v = bsq[proj][oc0], b1v = bsq[proj][oc0 + 1];
                ((uint32_t*)dst)[(size_t)pxg  * 16 + nb * 4 + t] =
                    bf16x2_of(C[nb][0] + b0v, C[nb][1] + b1v);
                ((uint32_t*)dst)[(size_t)pxg8 * 16 + nb * 4 + t] =
                    bf16x2_of(C[nb][2] + b0v, C[nb][3] + b1v);
            }
        } else {
            int pxl = wid * 16 + g;
#pragma unroll
            for (int nb = 0; nb < 4; nb++) {
                int oc0 = nb * 8 + 2 * t;
                float b0v = bsq[2][oc0], b1v = bsq[2][oc0 + 1];
                vs[oc0 * 136 + pxl]           = __float2bfloat16_rn(C[nb][0] + b0v);
                vs[(oc0 + 1) * 136 + pxl]     = __float2bfloat16_rn(C[nb][1] + b1v);
                vs[oc0 * 136 + pxl + 8]       = __float2bfloat16_rn(C[nb][2] + b0v);
                vs[(oc0 + 1) * 136 + pxl + 8] = __float2bfloat16_rn(C[nb][3] + b1v);
            }
        }
    }
    __syncthreads();
    // v writeout: channel-major
    __nv_bfloat16* vout = br ? g_vx : g_vm;
    int px0 = blockIdx.x * 128;
    for (int i = tid; i < 512; i += 256) {
        int ch = i >> 4, part = i & 15;
        *(uint4*)(vout + (size_t)ch * 8192 + px0 + part * 8) =
            *(const uint4*)(vs + ch * 136 + part * 8);
    }
}

// ---------------- flash attention on mma.sync (unchanged, validated) ----------------
__global__ __launch_bounds__(256, 1) void flash_mma_kernel() {
    const __nv_bfloat16 *Qb, *Kb, *Vb;
    if (blockIdx.y == 0) { Qb = g_qm; Kb = g_km; Vb = g_vx; }
    else                 { Qb = g_qx; Kb = g_kx; Vb = g_vm; }

    __shared__ __align__(16) unsigned char smK[2][8192];
    __shared__ __align__(16) unsigned char smV[2][8192];

    int tid  = threadIdx.x;
    int wid  = tid >> 5;
    int lane = tid & 31;
    int g    = lane >> 2;
    int t    = lane & 3;

    uint32_t skb[2] = { smem_u32(smK[0]), smem_u32(smK[1]) };
    uint32_t svb[2] = { smem_u32(smV[0]), smem_u32(smV[1]) };

    int q0 = blockIdx.x * 128 + wid * 16;
    uint32_t qa[2][4];
#pragma unroll
    for (int ks = 0; ks < 2; ks++) {
        const __nv_bfloat16* r0 = Qb + (size_t)(q0 + g) * 32;
        const __nv_bfloat16* r1 = Qb + (size_t)(q0 + g + 8) * 32;
        qa[ks][0] = *(const uint32_t*)(r0 + 16 * ks + 2 * t);
        qa[ks][1] = *(const uint32_t*)(r1 + 16 * ks + 2 * t);
        qa[ks][2] = *(const uint32_t*)(r0 + 16 * ks + 8 + 2 * t);
        qa[ks][3] = *(const uint32_t*)(r1 + 16 * ks + 8 + 2 * t);
    }

    float ob[4][4];
#pragma unroll
    for (int i = 0; i < 4; i++)
#pragma unroll
        for (int j = 0; j < 4; j++) ob[i][j] = 0.f;
    float sum_lo = 0.f, sum_hi = 0.f;

    for (int i = tid; i < 512; i += 256) {
        int key = i >> 2, c = i & 3;
        cp_async16(skb[0] + key * 64 + (((c + (key >> 1)) & 3) << 4),
                   (const char*)(Kb + (size_t)key * 32) + c * 16);
    }
    for (int i = tid; i < 512; i += 256) {
        int d = i >> 4, c = i & 15;
        cp_async16(svb[0] + d * 256 + (((c + d) & 15) << 4),
                   (const char*)(Vb + (size_t)d * 8192) + c * 16);
    }
    asm volatile("cp.async.commit_group;" ::: "memory");

    const int NT = 64;
    for (int tt = 0; tt < NT; tt++) {
        asm volatile("cp.async.wait_group 0;" ::: "memory");
        __syncthreads();
        if (tt + 1 < NT) {
            int nb2 = (tt + 1) & 1;
            int kb2 = (tt + 1) * 128;
            for (int i = tid; i < 512; i += 256) {
                int key = i >> 2, c = i & 3;
                cp_async16(skb[nb2] + key * 64 + (((c + (key >> 1)) & 3) << 4),
                           (const char*)(Kb + (size_t)(kb2 + key) * 32) + c * 16);
            }
            for (int i = tid; i < 512; i += 256) {
                int d = i >> 4, c = i & 15;
                cp_async16(svb[nb2] + d * 256 + (((c + d) & 15) << 4),
                           (const char*)(Vb + (size_t)d * 8192 + kb2) + c * 16);
            }
            asm volatile("cp.async.commit_group;" ::: "memory");
        }

        int buf = tt & 1;
        const uint32_t* kp = (const uint32_t*)smK[buf];
        const uint32_t* vp = (const uint32_t*)smV[buf];

        uint32_t pa[32];
#pragma unroll
        for (int nb = 0; nb < 16; nb++) {
            int key = nb * 8 + g;
            int rot = key >> 1;
            float c0 = 0.f, c1 = 0.f, c2 = 0.f, c3 = 0.f;
#pragma unroll
            for (int ks = 0; ks < 2; ks++) {
                uint32_t b0 = kp[key * 16 + (((2 * ks     + rot) & 3) << 2) + t];
                uint32_t b1 = kp[key * 16 + (((2 * ks + 1 + rot) & 3) << 2) + t];
                mma_bf16(c0, c1, c2, c3,
                         qa[ks][0], qa[ks][1], qa[ks][2], qa[ks][3],
                         b0, b1, c0, c1, c2, c3);
            }
            float e0 = __expf(c0), e1 = __expf(c1), e2 = __expf(c2), e3 = __expf(c3);
            sum_lo += e0 + e1;
            sum_hi += e2 + e3;
            int j = nb >> 1, h = nb & 1;
            pa[4 * j + 2 * h]     = bf16x2_of(e0, e1);
            pa[4 * j + 2 * h + 1] = bf16x2_of(e2, e3);
        }

#pragma unroll
        for (int j = 0; j < 8; j++) {
#pragma unroll
            for (int nbd = 0; nbd < 4; nbd++) {
                int d = nbd * 8 + g;
                uint32_t b0 = vp[d * 64 + (((2 * j     + d) & 15) << 2) + t];
                uint32_t b1 = vp[d * 64 + (((2 * j + 1 + d) & 15) << 2) + t];
                mma_bf16(ob[nbd][0], ob[nbd][1], ob[nbd][2], ob[nbd][3],
                         pa[4 * j], pa[4 * j + 1], pa[4 * j + 2], pa[4 * j + 3],
                         b0, b1,
                         ob[nbd][0], ob[nbd][1], ob[nbd][2], ob[nbd][3]);
            }
        }
    }

    sum_lo += __shfl_xor_sync(0xFFFFFFFFu, sum_lo, 1);
    sum_lo += __shfl_xor_sync(0xFFFFFFFFu, sum_lo, 2);
    sum_hi += __shfl_xor_sync(0xFFFFFFFFu, sum_hi, 1);
    sum_hi += __shfl_xor_sync(0xFFFFFFFFu, sum_hi, 2);
    float invLo = 1.0f / sum_lo;
    float invHi = 1.0f / sum_hi;

    float* base = g_attc + (size_t)blockIdx.y * 8192 * 32;
    float* rowA = base + (size_t)(q0 + g) * 32;
    float* rowB = base + (size_t)(q0 + g + 8) * 32;
#pragma unroll
    for (int nbd = 0; nbd < 4; nbd++) {
        int d = nbd * 8 + 2 * t;
        *(float2*)(rowA + d) = make_float2(ob[nbd][0] * invLo, ob[nbd][1] * invLo);
        *(float2*)(rowB + d) = make_float2(ob[nbd][2] * invHi, ob[nbd][3] * invHi);
    }
}

// ---------------- multi residual 1x1 + relu (no att) -> out ch 32..63 ----------------
__global__ __launch_bounds__(256) void xr_conv_kernel(
    const float* __restrict__ cv, const float* __restrict__ w,
    const float* __restrict__ b, float* __restrict__ out)
{
    __shared__ __align__(16) float wt[1024];
    __shared__ float bsm[32];
    int tid = threadIdx.x;
    for (int i = tid; i < 1024; i += 256) {
        int oc = i >> 5, ic = i & 31;
        wt[ic * 32 + oc] = w[oc * 32 + ic];
    }
    if (tid < 32) bsm[tid] = b[tid];
    __syncthreads();

    int px = blockIdx.x * 256 + tid;
    ull acc[16];
#pragma unroll
    for (int p = 0; p < 16; p++) acc[p] = pack2(bsm[2 * p], bsm[2 * p + 1]);
    for (int ic = 0; ic < 32; ic++) {
        float x = cv[(size_t)ic * 131072 + px];
        ull x2 = pack2(x, x);
        const ulonglong2* wp = (const ulonglong2*)(wt + ic * 32);
#pragma unroll
        for (int p2 = 0; p2 < 8; p2++) {
            ulonglong2 wv = wp[p2];
            acc[2 * p2]     = ffma2(x2, wv.x, acc[2 * p2]);
            acc[2 * p2 + 1] = ffma2(x2, wv.y, acc[2 * p2 + 1]);
        }
    }
#pragma unroll
    for (int p = 0; p < 16; p++) {
        float va, vb; unpack2(acc[p], va, vb);
        int oc = 2 * p;
        out[(size_t)(32 + oc) * 131072 + px] = fmaxf(va, 0.f);
        out[(size_t)(33 + oc) * 131072 + px] = fmaxf(vb, 0.f);
    }
}

// ---------------- final: out[c][px] += gamma * upsampled attention ----------------
__global__ __launch_bounds__(256) void epi_final_kernel(
    float* __restrict__ out, const float* __restrict__ gammap)
{
    int px = blockIdx.x * 256 + threadIdx.x;
    float g = gammap[0];
    int yy = px >> 9, xx = px & 511;
    int fb = ((yy >> 2) * 128 + (xx >> 2)) * 32;
    const float* a0 = g_attc + fb;             // multi_out -> ch 0..31
    const float* a1 = g_attc + 262144 + fb;    // mono_out  -> ch 32..63
#pragma unroll
    for (int c = 0; c < 32; c++) {
        out[(size_t)c * 131072 + px]        += g * a0[c];
        out[(size_t)(c + 32) * 131072 + px] += g * a1[c];
    }
}

// ---------------- host ----------------
#define SMEM_TILE (int)((2 * 32 * WP_N + 32 + 2 * 4 * 66 * TP_N) * 4)
#define SMEM_E    (int)((2 * 32 * WP_N + 32) * 4)

extern "C" void kernel_launch(void* const* d_in, const int* in_sizes, int n_in,
                              void* d_out, int out_size) {
    const float* mono  = (const float*)d_in[0];
    const float* cv    = (const float*)d_in[1];
    const float* me_w1 = (const float*)d_in[2];  const float* me_b1 = (const float*)d_in[3];
    const float* me_w2 = (const float*)d_in[4];  const float* me_b2 = (const float*)d_in[5];
    const float* xe_w1 = (const float*)d_in[6];  const float* xe_b1 = (const float*)d_in[7];
    const float* xe_w2 = (const float*)d_in[8];  const float* xe_b2 = (const float*)d_in[9];
    const float* mq_w  = (const float*)d_in[10]; const float* mq_b  = (const float*)d_in[11];
    const float* mk_w  = (const float*)d_in[12]; const float* mk_b  = (const float*)d_in[13];
    const float* mv_w  = (const float*)d_in[14]; const float* mv_b  = (const float*)d_in[15];
    const float* xq_w  = (const float*)d_in[16]; const float* xq_b  = (const float*)d_in[17];
    const float* xk_w  = (const float*)d_in[18]; const float* xk_b  = (const float*)d_in[19];
    const float* xv_w  = (const float*)d_in[20]; const float* xv_b  = (const float*)d_in[21];
    const float* mr_w1 = (const float*)d_in[22]; const float* mr_b1 = (const float*)d_in[23];
    const float* mr_w2 = (const float*)d_in[24]; const float* mr_b2 = (const float*)d_in[25];
    const float* xr_w  = (const float*)d_in[26]; const float* xr_b  = (const float*)d_in[27];
    const float* gamma = (const float*)d_in[28];
    float* out = (float*)d_out;

    static cudaStream_t s2 = nullptr;
    static cudaEvent_t evA = nullptr, evB = nullptr;
    static int init_done = 0;
    if (!init_done) {
        cudaStreamCreateWithFlags(&s2, cudaStreamNonBlocking);
        cudaEventCreateWithFlags(&evA, cudaEventDisableTiming);
        cudaEventCreateWithFlags(&evB, cudaEventDisableTiming);
        cudaFuncSetAttribute(hconv_kernel<2, 0, 0>, cudaFuncAttributeMaxDynamicSharedMemorySize, SMEM_E);
        cudaFuncSetAttribute(hconv_kernel<2, 1, 0>, cudaFuncAttributeMaxDynamicSharedMemorySize, SMEM_E);
        cudaFuncSetAttribute(hconv_kernel<1, 0, 1>, cudaFuncAttributeMaxDynamicSharedMemorySize, SMEM_TILE);
        cudaFuncSetAttribute(hconv_kernel<1, 2, 1>, cudaFuncAttributeMaxDynamicSharedMemorySize, SMEM_TILE);
        init_done = 1;
    }

    void *p_mh, *p_ml, *p_ch, *p_cl, *p_c1mh, *p_c1ml, *p_c1xh, *p_c1xl;
    void *p_fm, *p_fx, *p_r1h, *p_r1l;
    cudaGetSymbolAddress(&p_mh, g_mono_hi);  cudaGetSymbolAddress(&p_ml, g_mono_lo);
    cudaGetSymbolAddress(&p_ch, g_cv_hi);    cudaGetSymbolAddress(&p_cl, g_cv_lo);
    cudaGetSymbolAddress(&p_c1mh, g_c1m_hi); cudaGetSymbolAddress(&p_c1ml, g_c1m_lo);
    cudaGetSymbolAddress(&p_c1xh, g_c1x_hi); cudaGetSymbolAddress(&p_c1xl, g_c1x_lo);
    cudaGetSymbolAddress(&p_fm, g_featm);    cudaGetSymbolAddress(&p_fx, g_featx);
    cudaGetSymbolAddress(&p_r1h, g_r1_hi);   cudaGetSymbolAddress(&p_r1l, g_r1_lo);

    // 0. pre-pack weights
    PrepArgs pp;
    pp.cw[0] = me_w1; pp.cw[1] = xe_w1; pp.cw[2] = me_w2; pp.cw[3] = xe_w2;
    pp.cw[4] = mr_w1; pp.cw[5] = mr_w2;
    pp.qw[0] = mq_w; pp.qw[1] = mk_w; pp.qw[2] = mv_w;
    pp.qw[3] = xq_w; pp.qw[4] = xk_w; pp.qw[5] = xv_w;
    prep_kernel<<<32, 256>>>(pp);

    // 1. transpose inputs
    to_pm_kernel<<<dim3(512, 2), 256>>>(mono, cv);

    // ---- fork: residual branch on s2 ----
    cudaEventRecord(evA, 0);
    cudaStreamWaitEvent(s2, evA, 0);

    // s2: mono residual conv1 -> r1 hi/lo
    HCArgs r1{};
    r1.ih0 = (const __nv_bfloat16*)p_mh; r1.il0 = (const __nv_bfloat16*)p_ml;
    r1.b0 = mr_b1;
    r1.oh0 = p_r1h; r1.ol0 = p_r1l;
    r1.wset = 4;
    r1.Hin = 256; r1.Win = 512; r1.Wout = 512; r1.wsh = 9;
    hconv_kernel<1, 0, 1><<<dim3(1024, 1), 256, SMEM_TILE, s2>>>(r1);

    // s2: mono residual conv2 -> out ch 0..31 (relu, no att)
    HCArgs r2{};
    r2.ih0 = (const __nv_bfloat16*)p_r1h; r2.il0 = (const __nv_bfloat16*)p_r1l;
    r2.b0 = mr_b2;
    r2.outf = out;
    r2.wset = 5;
    r2.Hin = 256; r2.Win = 512; r2.Wout = 512; r2.wsh = 9;
    hconv_kernel<1, 2, 1><<<dim3(1024, 1), 256, SMEM_TILE, s2>>>(r2);

    // s2: multi residual 1x1 -> out ch 32..63 (relu, no att)
    xr_conv_kernel<<<512, 256, 0, s2>>>(cv, xr_w, xr_b, out);
    cudaEventRecord(evB, s2);

    // stream 0: attention branch
    HCArgs e1{};
    e1.ih0 = (const __nv_bfloat16*)p_mh; e1.il0 = (const __nv_bfloat16*)p_ml;
    e1.ih1 = (const __nv_bfloat16*)p_ch; e1.il1 = (const __nv_bfloat16*)p_cl;
    e1.b0 = me_b1; e1.b1 = xe_b1;
    e1.oh0 = p_c1mh; e1.ol0 = p_c1ml; e1.oh1 = p_c1xh; e1.ol1 = p_c1xl;
    e1.wset = 0;
    e1.Hin = 256; e1.Win = 512; e1.Wout = 256; e1.wsh = 8;
    hconv_kernel<2, 0, 0><<<dim3(256, 2), 256, SMEM_E>>>(e1);

    HCArgs e2{};
    e2.ih0 = (const __nv_bfloat16*)p_c1mh; e2.il0 = (const __nv_bfloat16*)p_c1ml;
    e2.ih1 = (const __nv_bfloat16*)p_c1xh; e2.il1 = (const __nv_bfloat16*)p_c1xl;
    e2.b0 = me_b2; e2.b1 = xe_b2;
    e2.oh0 = p_fm; e2.oh1 = p_fx;
    e2.wset = 2;
    e2.Hin = 128; e2.Win = 256; e2.Wout = 128; e2.wsh = 7;
    hconv_kernel<2, 1, 0><<<dim3(64, 2), 256, SMEM_E>>>(e2);

    QkvHArgs qa;
    qa.b[0] = mq_b; qa.b[1] = mk_b; qa.b[2] = mv_b;
    qa.b[3] = xq_b; qa.b[4] = xk_b; qa.b[5] = xv_b;
    qkvh_kernel<<<dim3(64, 2), 256>>>(qa);

    flash_mma_kernel<<<dim3(64, 2), 256>>>();

    // ---- join + final epilogue ----
    cudaStreamWaitEvent(0, evB, 0);
    epi_final_kernel<<<512, 256>>>(out, gamma);
}